// round 2
// baseline (speedup 1.0000x reference)
#include <cuda_runtime.h>
#include <cuda_bf16.h>
#include <cstdint>

// Problem constants
#define BB 4
#define SS 4096
#define DD 2048
#define EE 64
#define CAP 128
#define M_TOT (BB*SS)          // 16384 tokens
#define OFF_MAXP (M_TOT*EE)    // offset of max_probs in d_out

// GEMM tiling
#define MT 64                  // tokens per CTA
#define KT 32                  // k per tile
#define SROW 68                // smem floats per k-row (padded, keeps 16B align)

__device__ __align__(16) unsigned char g_eidx[M_TOT];

__global__ __launch_bounds__(128) void router_gemm_softmax(
    const float* __restrict__ A,     // [M_TOT, DD]
    const float* __restrict__ W,     // [EE, DD]
    const float* __restrict__ bias,  // [EE]
    float* __restrict__ out)         // d_out base; max_probs at +OFF_MAXP
{
    __shared__ float sA[2][KT * SROW];
    __shared__ float sW[2][KT * SROW];

    const int tid  = threadIdx.x;
    const int tn   = tid & 7;       // 0..7  -> n0 = tn*8
    const int tm   = tid >> 3;      // 0..15 -> m0 = tm*4
    const int m0   = tm * 4;
    const int n0   = tn * 8;
    const long base_m = (long)blockIdx.x * MT;

    const float4* __restrict__ A4 = (const float4*)A;
    const float4* __restrict__ W4 = (const float4*)W;

    float acc[4][8];
#pragma unroll
    for (int i = 0; i < 4; i++)
#pragma unroll
        for (int j = 0; j < 8; j++) acc[i][j] = 0.0f;

    float4 pa[4], pw[4];

    // ---- load tile 0 ----
#pragma unroll
    for (int i = 0; i < 4; i++) {
        int fid = i * 128 + tid;
        int r  = fid >> 3;        // row within tile (token row / expert row)
        int kq = fid & 7;         // float4 index within 32-float row chunk
        pa[i] = A4[(base_m + r) * (DD / 4) + kq];
        pw[i] = W4[(long)r * (DD / 4) + kq];
    }
    {
#pragma unroll
        for (int i = 0; i < 4; i++) {
            int fid = i * 128 + tid;
            int r  = fid >> 3;
            int k  = (fid & 7) * 4;
            sA[0][(k + 0) * SROW + r] = pa[i].x;
            sA[0][(k + 1) * SROW + r] = pa[i].y;
            sA[0][(k + 2) * SROW + r] = pa[i].z;
            sA[0][(k + 3) * SROW + r] = pa[i].w;
            sW[0][(k + 0) * SROW + r] = pw[i].x;
            sW[0][(k + 1) * SROW + r] = pw[i].y;
            sW[0][(k + 2) * SROW + r] = pw[i].z;
            sW[0][(k + 3) * SROW + r] = pw[i].w;
        }
    }
    __syncthreads();

    int buf = 0;
    const int NTILES = DD / KT;   // 64
    for (int t = 0; t < NTILES; t++) {
        // prefetch next tile into registers
        if (t < NTILES - 1) {
            int kq0 = ((t + 1) * KT) >> 2;
#pragma unroll
            for (int i = 0; i < 4; i++) {
                int fid = i * 128 + tid;
                int r  = fid >> 3;
                int kq = fid & 7;
                pa[i] = A4[(base_m + r) * (DD / 4) + kq0 + kq];
                pw[i] = W4[(long)r * (DD / 4) + kq0 + kq];
            }
        }
        // compute this tile
#pragma unroll 8
        for (int k = 0; k < KT; k++) {
            const float4 a  = *(const float4*)(&sA[buf][k * SROW + m0]);
            const float4 w0 = *(const float4*)(&sW[buf][k * SROW + n0]);
            const float4 w1 = *(const float4*)(&sW[buf][k * SROW + n0 + 4]);
            float av[4] = {a.x, a.y, a.z, a.w};
            float wv[8] = {w0.x, w0.y, w0.z, w0.w, w1.x, w1.y, w1.z, w1.w};
#pragma unroll
            for (int im = 0; im < 4; im++)
#pragma unroll
                for (int jn = 0; jn < 8; jn++)
                    acc[im][jn] = fmaf(av[im], wv[jn], acc[im][jn]);
        }
        // store prefetched tile into other buffer
        if (t < NTILES - 1) {
            int nb = buf ^ 1;
#pragma unroll
            for (int i = 0; i < 4; i++) {
                int fid = i * 128 + tid;
                int r  = fid >> 3;
                int k  = (fid & 7) * 4;
                sA[nb][(k + 0) * SROW + r] = pa[i].x;
                sA[nb][(k + 1) * SROW + r] = pa[i].y;
                sA[nb][(k + 2) * SROW + r] = pa[i].z;
                sA[nb][(k + 3) * SROW + r] = pa[i].w;
                sW[nb][(k + 0) * SROW + r] = pw[i].x;
                sW[nb][(k + 1) * SROW + r] = pw[i].y;
                sW[nb][(k + 2) * SROW + r] = pw[i].z;
                sW[nb][(k + 3) * SROW + r] = pw[i].w;
            }
            __syncthreads();
            buf = nb;
        }
    }

    // ---- epilogue: +bias, softmax-max, argmax ----
    float bv[8];
#pragma unroll
    for (int j = 0; j < 8; j++) bv[j] = bias[n0 + j];

#pragma unroll
    for (int im = 0; im < 4; im++) {
#pragma unroll
        for (int j = 0; j < 8; j++) acc[im][j] += bv[j];

        // local max + argmax (first index wins on tie)
        float mx = acc[im][0];
        int   ag = n0;
#pragma unroll
        for (int j = 1; j < 8; j++) {
            if (acc[im][j] > mx) { mx = acc[im][j]; ag = n0 + j; }
        }
        // butterfly over the 8 lanes of this token group
#pragma unroll
        for (int d = 1; d < 8; d <<= 1) {
            float omx = __shfl_xor_sync(0xffffffffu, mx, d);
            int   oag = __shfl_xor_sync(0xffffffffu, ag, d);
            if (omx > mx || (omx == mx && oag < ag)) { mx = omx; ag = oag; }
        }
        // stable softmax denominator
        float s = 0.0f;
#pragma unroll
        for (int j = 0; j < 8; j++) s += expf(acc[im][j] - mx);
#pragma unroll
        for (int d = 1; d < 8; d <<= 1) s += __shfl_xor_sync(0xffffffffu, s, d);

        if (tn == 0) {
            long tok = base_m + m0 + im;
            out[OFF_MAXP + tok] = 1.0f / s;      // exp(mx-mx)/sum
            g_eidx[tok] = (unsigned char)ag;
        }
    }
}

// One block per (expert e, batch b): prefix-scan of matches over S, write the
// whole [S] column of expert_indices for that e (covers every output element).
__global__ __launch_bounds__(256) void capacity_scan(float* __restrict__ out)
{
    const int e = blockIdx.x;
    const int b = blockIdx.y;
    const int tid = threadIdx.x;
    const int lane = tid & 31;
    const int wid = tid >> 5;

    const uint4* ids4 = (const uint4*)(g_eidx + b * SS);
    uint4 raw = ids4[tid];
    unsigned char v[16];
    *(uint4*)v = raw;

    int c = 0;
#pragma unroll
    for (int j = 0; j < 16; j++) c += (v[j] == (unsigned char)e);

    // inclusive warp scan
    int inc = c;
#pragma unroll
    for (int d = 1; d < 32; d <<= 1) {
        int o = __shfl_up_sync(0xffffffffu, inc, d);
        if (lane >= d) inc += o;
    }
    __shared__ int ws[8];
    if (lane == 31) ws[wid] = inc;
    __syncthreads();
    int wpre = 0;
#pragma unroll
    for (int w = 0; w < 8; w++) wpre += (w < wid) ? ws[w] : 0;

    int run = wpre + inc - c;   // exclusive prefix for this thread's 16 slots
    long ob = ((long)(b * SS + tid * 16)) * EE + e;
#pragma unroll
    for (int j = 0; j < 16; j++) {
        bool m = (v[j] == (unsigned char)e);
        if (m) run++;
        out[ob + (long)j * EE] = (m && run <= CAP) ? 1.0f : 0.0f;
    }
}

extern "C" void kernel_launch(void* const* d_in, const int* in_sizes, int n_in,
                              void* d_out, int out_size)
{
    const float* A    = (const float*)d_in[0];  // hidden_states [4,4096,2048]
    const float* W    = (const float*)d_in[1];  // [64,2048]
    const float* bias = (const float*)d_in[2];  // [64]
    float* out = (float*)d_out;

    router_gemm_softmax<<<M_TOT / MT, 128>>>(A, W, bias, out);
    capacity_scan<<<dim3(EE, BB), 256>>>(out);
}

// round 4
// speedup vs baseline: 1.0722x; 1.0722x over previous
#include <cuda_runtime.h>
#include <cstdint>

#define BB 4
#define SS 4096
#define DD 2048
#define EE 64
#define CAP 128
#define M_TOT (BB*SS)          // 16384 tokens
#define OFF_MAXP (M_TOT*EE)    // offset of max_probs in d_out

#define BM 128
#define BK 32
#define NTILES (DD/BK)         // 64
#define AR 36                  // sA row stride in floats (conflict-free)
#define WR 68                  // sW row stride in floats
#define LR 68                  // slog row stride

#define TAU 1e-3f
#define MAXFIX 4096

__device__ __align__(16) unsigned char g_eidx[M_TOT];
__device__ int g_cnt = 0;
__device__ int g_list[MAXFIX];

__device__ __forceinline__ void cvt_tf32(unsigned &u, float f) {
    asm("cvt.rna.tf32.f32 %0, %1;" : "=r"(u) : "f"(f));
}
__device__ __forceinline__ void split2(float v, unsigned &hi, unsigned &lo) {
    cvt_tf32(hi, v);
    float l = v - __uint_as_float(hi);
    cvt_tf32(lo, l);
}
__device__ __forceinline__ void mma8(float c[4],
                                     unsigned a0, unsigned a1, unsigned a2, unsigned a3,
                                     unsigned b0, unsigned b1) {
    asm volatile("mma.sync.aligned.m16n8k8.row.col.f32.tf32.tf32.f32 "
                 "{%0,%1,%2,%3}, {%4,%5,%6,%7}, {%8,%9}, {%0,%1,%2,%3};"
                 : "+f"(c[0]), "+f"(c[1]), "+f"(c[2]), "+f"(c[3])
                 : "r"(a0), "r"(a1), "r"(a2), "r"(a3), "r"(b0), "r"(b1));
}

__global__ __launch_bounds__(128, 1) void router_mma(
    const float* __restrict__ A,     // [M_TOT, DD]
    const float* __restrict__ W,     // [EE, DD]
    const float* __restrict__ bias,  // [EE]
    float* __restrict__ out)
{
    __shared__ float sm[8768];        // 35072 B
    float* sA    = sm;                // [BM][AR] raw fp32 A tile
    float* sW    = sm + BM * AR;      // [BK][WR] raw fp32 W tile (k-major)
    float* slog  = sm;                // epilogue reuse: [BM][LR]
    float* sbias = sm + 8704;         // 64 floats

    const int tid  = threadIdx.x;
    const int lane = tid & 31;
    const int wid  = tid >> 5;
    const int wm   = wid & 1;
    const int wn   = wid >> 1;
    const int g    = lane >> 2;
    const int c    = lane & 3;
    const int blk  = blockIdx.x * BM;

    if (tid < EE) sbias[tid] = bias[tid];

    const float4* __restrict__ A4 = (const float4*)A;
    const float4* __restrict__ W4 = (const float4*)W;
    const int e = tid & 63;
    const int h = tid >> 6;

    float acc[4][4][4];
#pragma unroll
    for (int mt = 0; mt < 4; mt++)
#pragma unroll
        for (int nt = 0; nt < 4; nt++)
#pragma unroll
            for (int q = 0; q < 4; q++) acc[mt][nt][q] = 0.0f;

    float4 pa[8], pw[4];

#pragma unroll
    for (int l = 0; l < 8; l++) {
        int fi = l * 128 + tid;
        int row = fi >> 3, kq = fi & 7;
        pa[l] = A4[(blk + row) * (DD / 4) + kq];
    }
#pragma unroll
    for (int j = 0; j < 4; j++) pw[j] = W4[e * (DD / 4) + h * 4 + j];

#pragma unroll
    for (int l = 0; l < 8; l++) {
        int fi = l * 128 + tid;
        int row = fi >> 3, kq = fi & 7;
        *(float4*)&sA[row * AR + kq * 4] = pa[l];
    }
#pragma unroll
    for (int j = 0; j < 4; j++) {
        sW[(h * 16 + j * 4 + 0) * WR + e] = pw[j].x;
        sW[(h * 16 + j * 4 + 1) * WR + e] = pw[j].y;
        sW[(h * 16 + j * 4 + 2) * WR + e] = pw[j].z;
        sW[(h * 16 + j * 4 + 3) * WR + e] = pw[j].w;
    }
    __syncthreads();

    for (int t = 0; t < NTILES; t++) {
        if (t + 1 < NTILES) {
            int k0 = (t + 1) * 8;
#pragma unroll
            for (int l = 0; l < 8; l++) {
                int fi = l * 128 + tid;
                int row = fi >> 3, kq = fi & 7;
                pa[l] = A4[(blk + row) * (DD / 4) + k0 + kq];
            }
#pragma unroll
            for (int j = 0; j < 4; j++) pw[j] = W4[e * (DD / 4) + k0 + h * 4 + j];
        }

#pragma unroll
        for (int kc = 0; kc < 4; kc++) {
            const int k8 = kc * 8;
            unsigned ah[4][4], al[4][4];
#pragma unroll
            for (int mt = 0; mt < 4; mt++) {
                int rb = wm * 64 + mt * 16 + g;
                float r0 = sA[(rb    ) * AR + k8 + c];
                float r1 = sA[(rb + 8) * AR + k8 + c];
                float r2 = sA[(rb    ) * AR + k8 + c + 4];
                float r3 = sA[(rb + 8) * AR + k8 + c + 4];
                split2(r0, ah[mt][0], al[mt][0]);
                split2(r1, ah[mt][1], al[mt][1]);
                split2(r2, ah[mt][2], al[mt][2]);
                split2(r3, ah[mt][3], al[mt][3]);
            }
            unsigned bh[4][2], bl[4][2];
#pragma unroll
            for (int nt = 0; nt < 4; nt++) {
                int cb = wn * 32 + nt * 8 + g;
                float q0 = sW[(k8 + c    ) * WR + cb];
                float q1 = sW[(k8 + c + 4) * WR + cb];
                split2(q0, bh[nt][0], bl[nt][0]);
                split2(q1, bh[nt][1], bl[nt][1]);
            }
#pragma unroll
            for (int mt = 0; mt < 4; mt++)
#pragma unroll
                for (int nt = 0; nt < 4; nt++) {
                    mma8(acc[mt][nt], ah[mt][0], ah[mt][1], ah[mt][2], ah[mt][3],
                         bh[nt][0], bh[nt][1]);
                    mma8(acc[mt][nt], ah[mt][0], ah[mt][1], ah[mt][2], ah[mt][3],
                         bl[nt][0], bl[nt][1]);
                    mma8(acc[mt][nt], al[mt][0], al[mt][1], al[mt][2], al[mt][3],
                         bh[nt][0], bh[nt][1]);
                }
        }
        __syncthreads();

        if (t + 1 < NTILES) {
#pragma unroll
            for (int l = 0; l < 8; l++) {
                int fi = l * 128 + tid;
                int row = fi >> 3, kq = fi & 7;
                *(float4*)&sA[row * AR + kq * 4] = pa[l];
            }
#pragma unroll
            for (int j = 0; j < 4; j++) {
                sW[(h * 16 + j * 4 + 0) * WR + e] = pw[j].x;
                sW[(h * 16 + j * 4 + 1) * WR + e] = pw[j].y;
                sW[(h * 16 + j * 4 + 2) * WR + e] = pw[j].z;
                sW[(h * 16 + j * 4 + 3) * WR + e] = pw[j].w;
            }
            __syncthreads();
        }
    }

    // ---- epilogue: dump logits to smem (reused), then per-token scan ----
    __syncthreads();
#pragma unroll
    for (int mt = 0; mt < 4; mt++)
#pragma unroll
        for (int nt = 0; nt < 4; nt++) {
            int r  = wm * 64 + mt * 16 + g;
            int cc = wn * 32 + nt * 8 + 2 * c;
            *(float2*)&slog[r * LR + cc]       = make_float2(acc[mt][nt][0], acc[mt][nt][1]);
            *(float2*)&slog[(r + 8) * LR + cc] = make_float2(acc[mt][nt][2], acc[mt][nt][3]);
        }
    __syncthreads();

    {
        const int tok = blk + tid;
        // zero-fill this token's expert_indices row (base for capacity_scan)
        float4 z = make_float4(0.f, 0.f, 0.f, 0.f);
        float4* zb = (float4*)(out + (long)tok * EE);
#pragma unroll
        for (int q = 0; q < 16; q++) zb[q] = z;

        const float* lr = slog + tid * LR;
        float mx = -1e30f, mx2 = -1e30f;
        int ag = 0;
#pragma unroll
        for (int j = 0; j < 16; j++) {
            float4 v = *(const float4*)(lr + 4 * j);
            float4 b = *(const float4*)(sbias + 4 * j);
            float xs[4] = {v.x + b.x, v.y + b.y, v.z + b.z, v.w + b.w};
#pragma unroll
            for (int q = 0; q < 4; q++) {
                float x = xs[q];
                if (x > mx)       { mx2 = mx; mx = x; ag = 4 * j + q; }
                else if (x > mx2) { mx2 = x; }
            }
        }
        float s = 0.0f;
#pragma unroll
        for (int j = 0; j < 16; j++) {
            float4 v = *(const float4*)(lr + 4 * j);
            float4 b = *(const float4*)(sbias + 4 * j);
            s += __expf(v.x + b.x - mx) + __expf(v.y + b.y - mx)
               + __expf(v.z + b.z - mx) + __expf(v.w + b.w - mx);
        }
        out[OFF_MAXP + tok] = 1.0f / s;
        g_eidx[tok] = (unsigned char)ag;

        if (mx - mx2 < TAU) {
            int p = atomicAdd(&g_cnt, 1);
            if (p < MAXFIX) g_list[p] = tok;
        }
    }
}

// Exact (double-single) recompute of the 64 logits for near-tie tokens;
// overwrites g_eidx with the exact argmax.
__global__ __launch_bounds__(512) void fixup_argmax(
    const float* __restrict__ A, const float* __restrict__ W,
    const float* __restrict__ bias)
{
    __shared__ float ph[512], pl[512];
    __shared__ double dl[64];

    int n = g_cnt;
    if (n > MAXFIX) n = MAXFIX;
    const int e   = threadIdx.x >> 3;   // expert 0..63
    const int sub = threadIdx.x & 7;    // k-slice 0..7 (256 elems each)

    for (int i = blockIdx.x; i < n; i += gridDim.x) {
        int tok = g_list[i];
        const float* a = A + (long)tok * DD + sub * 256;
        const float* w = W + (long)e   * DD + sub * 256;
        float shi = 0.f, slo = 0.f;
        for (int k = 0; k < 256; k++) {
            float av = __ldg(a + k), wv = __ldg(w + k);
            float p  = __fmul_rn(av, wv);
            float pe = __fmaf_rn(av, wv, -p);     // exact product residual
            float t  = shi + p;                   // TwoSum
            float bb = t - shi;
            float er = (shi - (t - bb)) + (p - bb);
            shi = t;
            slo = slo + (er + pe);
        }
        ph[threadIdx.x] = shi;
        pl[threadIdx.x] = slo;
        __syncthreads();
        if (threadIdx.x < 64) {
            double s = (double)bias[threadIdx.x];
            for (int j = 0; j < 8; j++)
                s += (double)ph[threadIdx.x * 8 + j] + (double)pl[threadIdx.x * 8 + j];
            dl[threadIdx.x] = s;
        }
        __syncthreads();
        if (threadIdx.x == 0) {
            double mx = dl[0]; int ag = 0;
            for (int j = 1; j < 64; j++)
                if (dl[j] > mx) { mx = dl[j]; ag = j; }   // first index wins ties
            g_eidx[tok] = (unsigned char)ag;
        }
        __syncthreads();
    }
}

// One block per (expert e, batch b): prefix-scan of matches over S; writes ONLY
// the 1.0 entries (expert_indices base was zero-filled by router_mma).
__global__ __launch_bounds__(256) void capacity_scan(float* __restrict__ out)
{
    const int e = blockIdx.x;
    const int b = blockIdx.y;
    const int tid = threadIdx.x;
    const int lane = tid & 31;
    const int wid = tid >> 5;

    const uint4* ids4 = (const uint4*)(g_eidx + b * SS);
    uint4 raw = ids4[tid];
    unsigned char v[16];
    *(uint4*)v = raw;

    int cnum = 0;
#pragma unroll
    for (int j = 0; j < 16; j++) cnum += (v[j] == (unsigned char)e);

    int inc = cnum;
#pragma unroll
    for (int d = 1; d < 32; d <<= 1) {
        int o = __shfl_up_sync(0xffffffffu, inc, d);
        if (lane >= d) inc += o;
    }
    __shared__ int ws[8];
    if (lane == 31) ws[wid] = inc;
    __syncthreads();
    int wpre = 0;
#pragma unroll
    for (int w = 0; w < 8; w++) wpre += (w < wid) ? ws[w] : 0;

    int run = wpre + inc - cnum;
    long tok0 = (long)b * SS + tid * 16;
#pragma unroll
    for (int j = 0; j < 16; j++) {
        if (v[j] == (unsigned char)e) {
            run++;
            if (run <= CAP) out[(tok0 + j) * EE + e] = 1.0f;
        }
    }

    // reset worklist counter for the next (graph-replayed) run
    if (e == 0 && b == 0 && tid == 0) g_cnt = 0;
}

extern "C" void kernel_launch(void* const* d_in, const int* in_sizes, int n_in,
                              void* d_out, int out_size)
{
    const float* A    = (const float*)d_in[0];
    const float* W    = (const float*)d_in[1];
    const float* bias = (const float*)d_in[2];
    float* out = (float*)d_out;

    router_mma<<<M_TOT / BM, 128>>>(A, W, bias, out);
    fixup_argmax<<<64, 512>>>(A, W, bias);
    capacity_scan<<<dim3(EE, BB), 256>>>(out);
}

// round 5
// speedup vs baseline: 1.2374x; 1.1541x over previous
#include <cuda_runtime.h>
#include <cuda_bf16.h>
#include <cstdint>

#define BB 4
#define SS 4096
#define DD 2048
#define EE 64
#define CAP 128
#define M_TOT (BB*SS)          // 16384 tokens
#define OFF_MAXP (M_TOT*EE)    // offset of max_probs in d_out

#define BM 128
#define BK 32
#define NTILES (DD/BK)         // 64
#define KPR 20                 // u32 (bf16x2) row stride: conflict-free
#define LR 68                  // slog f32 row stride

#define TAU 2e-4f
#define MAXFIX 4096

__device__ __align__(16) unsigned char g_eidx[M_TOT];
__device__ int g_cnt = 0;
__device__ int g_list[MAXFIX];

// split x,y into bf16 hi/lo pairs, packed as bf16x2 words (x low, y high)
__device__ __forceinline__ void split_pack(float x, float y, unsigned &hi, unsigned &lo) {
    __nv_bfloat16 hx = __float2bfloat16_rn(x);
    __nv_bfloat16 hy = __float2bfloat16_rn(y);
    float rx = x - __bfloat162float(hx);
    float ry = y - __bfloat162float(hy);
    __nv_bfloat16 lx = __float2bfloat16_rn(rx);
    __nv_bfloat16 ly = __float2bfloat16_rn(ry);
    __nv_bfloat162 H = __halves2bfloat162(hx, hy);
    __nv_bfloat162 L = __halves2bfloat162(lx, ly);
    hi = *reinterpret_cast<unsigned*>(&H);
    lo = *reinterpret_cast<unsigned*>(&L);
}

__device__ __forceinline__ void mma16(float c[4], const unsigned a[4],
                                      unsigned b0, unsigned b1) {
    asm volatile("mma.sync.aligned.m16n8k16.row.col.f32.bf16.bf16.f32 "
                 "{%0,%1,%2,%3}, {%4,%5,%6,%7}, {%8,%9}, {%0,%1,%2,%3};"
                 : "+f"(c[0]), "+f"(c[1]), "+f"(c[2]), "+f"(c[3])
                 : "r"(a[0]), "r"(a[1]), "r"(a[2]), "r"(a[3]), "r"(b0), "r"(b1));
}

__global__ __launch_bounds__(256, 1) void router_mma(
    const float* __restrict__ A,     // [M_TOT, DD]
    const float* __restrict__ W,     // [EE, DD]
    const float* __restrict__ bias,  // [EE]
    float* __restrict__ out)
{
    __shared__ __align__(16) unsigned char smbuf[35072];
    unsigned* sAh = (unsigned*)smbuf;              // [128][KPR]
    unsigned* sAl = sAh + BM * KPR;                // +2560
    unsigned* sWh = sAl + BM * KPR;                // +5120  [64][KPR]
    unsigned* sWl = sWh + EE * KPR;                // +6400
    float*    slog  = (float*)smbuf;               // epilogue reuse [128][LR]
    float*    sbias = (float*)smbuf + 8704;        // 64 floats

    const int tid  = threadIdx.x;
    const int lane = tid & 31;
    const int wid  = tid >> 5;
    const int wm   = wid & 3;         // 0..3 -> rows wm*32
    const int wn   = wid >> 2;        // 0..1 -> cols wn*32
    const int g    = lane >> 2;       // 0..7
    const int c    = lane & 3;        // 0..3
    const int blk  = blockIdx.x * BM;

    if (tid < EE) sbias[tid] = bias[tid];

    const float4* __restrict__ A4 = (const float4*)A;
    const float4* __restrict__ W4 = (const float4*)W;

    float acc[2][4][4];
#pragma unroll
    for (int mt = 0; mt < 2; mt++)
#pragma unroll
        for (int nt = 0; nt < 4; nt++)
#pragma unroll
            for (int q = 0; q < 4; q++) acc[mt][nt][q] = 0.0f;

    float4 pa[4], pw[2];

    // ---- preload tile 0 ----
#pragma unroll
    for (int l = 0; l < 4; l++) {
        int fi = l * 256 + tid;
        int row = fi >> 3, kq = fi & 7;
        pa[l] = A4[(long)(blk + row) * (DD / 4) + kq];
    }
#pragma unroll
    for (int l = 0; l < 2; l++) {
        int fi = l * 256 + tid;
        int row = fi >> 3, kq = fi & 7;
        pw[l] = W4[(long)row * (DD / 4) + kq];
    }

    // ---- stage tile 0 (split + pack) ----
#pragma unroll
    for (int l = 0; l < 4; l++) {
        int fi = l * 256 + tid;
        int row = fi >> 3, kq = fi & 7;
        unsigned h0, l0, h1, l1;
        split_pack(pa[l].x, pa[l].y, h0, l0);
        split_pack(pa[l].z, pa[l].w, h1, l1);
        sAh[row * KPR + 2 * kq] = h0;  sAh[row * KPR + 2 * kq + 1] = h1;
        sAl[row * KPR + 2 * kq] = l0;  sAl[row * KPR + 2 * kq + 1] = l1;
    }
#pragma unroll
    for (int l = 0; l < 2; l++) {
        int fi = l * 256 + tid;
        int row = fi >> 3, kq = fi & 7;
        unsigned h0, l0, h1, l1;
        split_pack(pw[l].x, pw[l].y, h0, l0);
        split_pack(pw[l].z, pw[l].w, h1, l1);
        sWh[row * KPR + 2 * kq] = h0;  sWh[row * KPR + 2 * kq + 1] = h1;
        sWl[row * KPR + 2 * kq] = l0;  sWl[row * KPR + 2 * kq + 1] = l1;
    }
    __syncthreads();

    for (int t = 0; t < NTILES; t++) {
        if (t + 1 < NTILES) {
            int k0 = (t + 1) * 8;
#pragma unroll
            for (int l = 0; l < 4; l++) {
                int fi = l * 256 + tid;
                int row = fi >> 3, kq = fi & 7;
                pa[l] = A4[(long)(blk + row) * (DD / 4) + k0 + kq];
            }
#pragma unroll
            for (int l = 0; l < 2; l++) {
                int fi = l * 256 + tid;
                int row = fi >> 3, kq = fi & 7;
                pw[l] = W4[(long)row * (DD / 4) + k0 + kq];
            }
        }

        // ---- compute: 2 k16 chunks ----
#pragma unroll
        for (int kc = 0; kc < 2; kc++) {
            const int kb = kc * 8;
            unsigned Ah[2][4], Al[2][4];
#pragma unroll
            for (int mt = 0; mt < 2; mt++) {
                int rb = (wm * 32 + mt * 16 + g) * KPR + kb + c;
                Ah[mt][0] = sAh[rb];
                Ah[mt][1] = sAh[rb + 8 * KPR];
                Ah[mt][2] = sAh[rb + 4];
                Ah[mt][3] = sAh[rb + 8 * KPR + 4];
                Al[mt][0] = sAl[rb];
                Al[mt][1] = sAl[rb + 8 * KPR];
                Al[mt][2] = sAl[rb + 4];
                Al[mt][3] = sAl[rb + 8 * KPR + 4];
            }
            unsigned Bh[4][2], Bl[4][2];
#pragma unroll
            for (int nt = 0; nt < 4; nt++) {
                int cb = (wn * 32 + nt * 8 + g) * KPR + kb + c;
                Bh[nt][0] = sWh[cb];  Bh[nt][1] = sWh[cb + 4];
                Bl[nt][0] = sWl[cb];  Bl[nt][1] = sWl[cb + 4];
            }
#pragma unroll
            for (int mt = 0; mt < 2; mt++)
#pragma unroll
                for (int nt = 0; nt < 4; nt++) {
                    mma16(acc[mt][nt], Ah[mt], Bh[nt][0], Bh[nt][1]);
                    mma16(acc[mt][nt], Ah[mt], Bl[nt][0], Bl[nt][1]);
                    mma16(acc[mt][nt], Al[mt], Bh[nt][0], Bh[nt][1]);
                }
        }
        __syncthreads();

        if (t + 1 < NTILES) {
#pragma unroll
            for (int l = 0; l < 4; l++) {
                int fi = l * 256 + tid;
                int row = fi >> 3, kq = fi & 7;
                unsigned h0, l0, h1, l1;
                split_pack(pa[l].x, pa[l].y, h0, l0);
                split_pack(pa[l].z, pa[l].w, h1, l1);
                sAh[row * KPR + 2 * kq] = h0;  sAh[row * KPR + 2 * kq + 1] = h1;
                sAl[row * KPR + 2 * kq] = l0;  sAl[row * KPR + 2 * kq + 1] = l1;
            }
#pragma unroll
            for (int l = 0; l < 2; l++) {
                int fi = l * 256 + tid;
                int row = fi >> 3, kq = fi & 7;
                unsigned h0, l0, h1, l1;
                split_pack(pw[l].x, pw[l].y, h0, l0);
                split_pack(pw[l].z, pw[l].w, h1, l1);
                sWh[row * KPR + 2 * kq] = h0;  sWh[row * KPR + 2 * kq + 1] = h1;
                sWl[row * KPR + 2 * kq] = l0;  sWl[row * KPR + 2 * kq + 1] = l1;
            }
            __syncthreads();
        }
    }

    // ---- epilogue: dump logits to smem, then per-token scan ----
    __syncthreads();
#pragma unroll
    for (int mt = 0; mt < 2; mt++)
#pragma unroll
        for (int nt = 0; nt < 4; nt++) {
            int r  = wm * 32 + mt * 16 + g;
            int cc = wn * 32 + nt * 8 + 2 * c;
            *(float2*)&slog[r * LR + cc]       = make_float2(acc[mt][nt][0], acc[mt][nt][1]);
            *(float2*)&slog[(r + 8) * LR + cc] = make_float2(acc[mt][nt][2], acc[mt][nt][3]);
        }
    __syncthreads();

    if (tid < BM) {
        const int tok = blk + tid;
        // zero-fill this token's expert_indices row (base for capacity_scan)
        float4 z = make_float4(0.f, 0.f, 0.f, 0.f);
        float4* zb = (float4*)(out + (long)tok * EE);
#pragma unroll
        for (int q = 0; q < 16; q++) zb[q] = z;

        const float* lr = slog + tid * LR;
        float mx = -1e30f, mx2 = -1e30f;
        int ag = 0;
#pragma unroll
        for (int j = 0; j < 16; j++) {
            float4 v = *(const float4*)(lr + 4 * j);
            float4 b = *(const float4*)(sbias + 4 * j);
            float xs[4] = {v.x + b.x, v.y + b.y, v.z + b.z, v.w + b.w};
#pragma unroll
            for (int q = 0; q < 4; q++) {
                float x = xs[q];
                if (x > mx)       { mx2 = mx; mx = x; ag = 4 * j + q; }
                else if (x > mx2) { mx2 = x; }
            }
        }
        float s = 0.0f;
#pragma unroll
        for (int j = 0; j < 16; j++) {
            float4 v = *(const float4*)(lr + 4 * j);
            float4 b = *(const float4*)(sbias + 4 * j);
            s += __expf(v.x + b.x - mx) + __expf(v.y + b.y - mx)
               + __expf(v.z + b.z - mx) + __expf(v.w + b.w - mx);
        }
        out[OFF_MAXP + tok] = 1.0f / s;
        g_eidx[tok] = (unsigned char)ag;

        if (mx - mx2 < TAU) {
            int p = atomicAdd(&g_cnt, 1);
            if (p < MAXFIX) g_list[p] = tok;
        }
    }
}

// Exact (double-single) recompute of the 64 logits for near-tie tokens;
// overwrites g_eidx with the exact argmax.
__global__ __launch_bounds__(512) void fixup_argmax(
    const float* __restrict__ A, const float* __restrict__ W,
    const float* __restrict__ bias)
{
    __shared__ float ph[512], pl[512];
    __shared__ double dl[64];

    int n = g_cnt;
    if (n > MAXFIX) n = MAXFIX;
    const int e   = threadIdx.x >> 3;   // expert 0..63
    const int sub = threadIdx.x & 7;    // k-slice 0..7 (256 elems each)

    for (int i = blockIdx.x; i < n; i += gridDim.x) {
        int tok = g_list[i];
        const float* a = A + (long)tok * DD + sub * 256;
        const float* w = W + (long)e   * DD + sub * 256;
        float shi = 0.f, slo = 0.f;
        for (int k = 0; k < 256; k++) {
            float av = __ldg(a + k), wv = __ldg(w + k);
            float p  = __fmul_rn(av, wv);
            float pe = __fmaf_rn(av, wv, -p);     // exact product residual
            float t  = shi + p;                   // TwoSum
            float bb = t - shi;
            float er = (shi - (t - bb)) + (p - bb);
            shi = t;
            slo = slo + (er + pe);
        }
        ph[threadIdx.x] = shi;
        pl[threadIdx.x] = slo;
        __syncthreads();
        if (threadIdx.x < 64) {
            double s = (double)bias[threadIdx.x];
            for (int j = 0; j < 8; j++)
                s += (double)ph[threadIdx.x * 8 + j] + (double)pl[threadIdx.x * 8 + j];
            dl[threadIdx.x] = s;
        }
        __syncthreads();
        if (threadIdx.x == 0) {
            double mx = dl[0]; int ag = 0;
            for (int j = 1; j < 64; j++)
                if (dl[j] > mx) { mx = dl[j]; ag = j; }   // first index wins ties
            g_eidx[tok] = (unsigned char)ag;
        }
        __syncthreads();
    }
}

// One block per (expert e, batch b): prefix-scan of matches over S; writes ONLY
// the 1.0 entries (expert_indices base was zero-filled by router_mma).
__global__ __launch_bounds__(256) void capacity_scan(float* __restrict__ out)
{
    const int e = blockIdx.x;
    const int b = blockIdx.y;
    const int tid = threadIdx.x;
    const int lane = tid & 31;
    const int wid = tid >> 5;

    const uint4* ids4 = (const uint4*)(g_eidx + b * SS);
    uint4 raw = ids4[tid];
    unsigned char v[16];
    *(uint4*)v = raw;

    int cnum = 0;
#pragma unroll
    for (int j = 0; j < 16; j++) cnum += (v[j] == (unsigned char)e);

    int inc = cnum;
#pragma unroll
    for (int d = 1; d < 32; d <<= 1) {
        int o = __shfl_up_sync(0xffffffffu, inc, d);
        if (lane >= d) inc += o;
    }
    __shared__ int ws[8];
    if (lane == 31) ws[wid] = inc;
    __syncthreads();
    int wpre = 0;
#pragma unroll
    for (int w = 0; w < 8; w++) wpre += (w < wid) ? ws[w] : 0;

    int run = wpre + inc - cnum;
    long tok0 = (long)b * SS + tid * 16;
#pragma unroll
    for (int j = 0; j < 16; j++) {
        if (v[j] == (unsigned char)e) {
            run++;
            if (run <= CAP) out[(tok0 + j) * EE + e] = 1.0f;
        }
    }

    // reset worklist counter for the next (graph-replayed) run
    if (e == 0 && b == 0 && tid == 0) g_cnt = 0;
}

extern "C" void kernel_launch(void* const* d_in, const int* in_sizes, int n_in,
                              void* d_out, int out_size)
{
    const float* A    = (const float*)d_in[0];
    const float* W    = (const float*)d_in[1];
    const float* bias = (const float*)d_in[2];
    float* out = (float*)d_out;

    router_mma<<<M_TOT / BM, 256>>>(A, W, bias, out);
    fixup_argmax<<<128, 512>>>(A, W, bias);
    capacity_scan<<<dim3(EE, BB), 256>>>(out);
}

// round 6
// speedup vs baseline: 1.3139x; 1.0618x over previous
#include <cuda_runtime.h>
#include <cuda_bf16.h>
#include <cstdint>

#define BB 4
#define SS 4096
#define DD 2048
#define EE 64
#define CAP 128
#define M_TOT (BB*SS)          // 16384 tokens
#define OFF_MAXP (M_TOT*EE)

#define BM 64
#define BK 32
#define NTILES (DD/BK)         // 64
#define KPR 20                 // u32 row stride in smem (conflict-free LDS)
#define LR 68

#define TAU 2e-4f
#define MAXFIX 4096

__device__ __align__(16) unsigned char g_eidx[M_TOT];
__device__ int g_cnt = 0;
__device__ int g_list[MAXFIX];
// pre-split W, tile-major: [tile t][row e][16 u32]  (u32 = bf16x2 over k-pairs)
__device__ __align__(16) unsigned gWh[NTILES * EE * 16];
__device__ __align__(16) unsigned gWl[NTILES * EE * 16];

__device__ __forceinline__ void split_pack(float x, float y, unsigned &hi, unsigned &lo) {
    __nv_bfloat16 hx = __float2bfloat16_rn(x);
    __nv_bfloat16 hy = __float2bfloat16_rn(y);
    float rx = x - __bfloat162float(hx);
    float ry = y - __bfloat162float(hy);
    __nv_bfloat16 lx = __float2bfloat16_rn(rx);
    __nv_bfloat16 ly = __float2bfloat16_rn(ry);
    __nv_bfloat162 H = __halves2bfloat162(hx, hy);
    __nv_bfloat162 L = __halves2bfloat162(lx, ly);
    hi = *reinterpret_cast<unsigned*>(&H);
    lo = *reinterpret_cast<unsigned*>(&L);
}

__device__ __forceinline__ void mma16(float c[4], const unsigned a[4],
                                      unsigned b0, unsigned b1) {
    asm volatile("mma.sync.aligned.m16n8k16.row.col.f32.bf16.bf16.f32 "
                 "{%0,%1,%2,%3}, {%4,%5,%6,%7}, {%8,%9}, {%0,%1,%2,%3};"
                 : "+f"(c[0]), "+f"(c[1]), "+f"(c[2]), "+f"(c[3])
                 : "r"(a[0]), "r"(a[1]), "r"(a[2]), "r"(a[3]), "r"(b0), "r"(b1));
}

// Pre-split W into bf16x2 hi/lo, tile-major layout.
__global__ __launch_bounds__(256) void split_w(const float* __restrict__ W)
{
    int e  = blockIdx.x >> 2;                 // 0..63
    int jg = (blockIdx.x & 3) * 256 + threadIdx.x;  // 0..1023 (k-pair)
    int k  = 2 * jg;
    float x = W[e * DD + k], y = W[e * DD + k + 1];
    unsigned h, l;
    split_pack(x, y, h, l);
    int t = jg >> 4, j = jg & 15;
    gWh[(t * EE + e) * 16 + j] = h;
    gWl[(t * EE + e) * 16 + j] = l;
}

__global__ __launch_bounds__(128, 2) void router_mma(
    const float* __restrict__ A,     // [M_TOT, DD]
    const float* __restrict__ bias,  // [EE]
    float* __restrict__ out)
{
    __shared__ __align__(16) unsigned smbuf[10240];   // 40 KB
    unsigned* sAh = smbuf;            // [2][64*KPR]
    unsigned* sAl = smbuf + 2560;
    unsigned* sWh = smbuf + 5120;
    unsigned* sWl = smbuf + 7680;
    float*    slog = (float*)smbuf;   // epilogue reuse [64][LR]
    __shared__ float sbias[EE];

    const int tid  = threadIdx.x;
    const int lane = tid & 31;
    const int wid  = tid >> 5;
    const int wm   = wid & 1;         // rows wm*32
    const int wn   = wid >> 1;        // cols wn*32
    const int g    = lane >> 2;
    const int c    = lane & 3;
    const int blk  = blockIdx.x * BM;

    if (tid < EE) sbias[tid] = bias[tid];

    const float4* __restrict__ A4 = (const float4*)A;
    const uint4*  gWh4 = (const uint4*)gWh;   // [t*256 + u]
    const uint4*  gWl4 = (const uint4*)gWl;

    const int arow = tid >> 1;                 // A LDG: 4 f4/thread
    const int akq0 = (tid & 1) * 4;

    float acc[2][4][4];
#pragma unroll
    for (int mt = 0; mt < 2; mt++)
#pragma unroll
        for (int nt = 0; nt < 4; nt++)
#pragma unroll
            for (int q = 0; q < 4; q++) acc[mt][nt][q] = 0.0f;

    float4 pa[4];
    uint4  pwh[2], pwl[2];

    // ---- LDG tile 0 ----
#pragma unroll
    for (int l = 0; l < 4; l++) {
        int fi = l * 128 + tid;
        int row = fi >> 3, kq = fi & 7;
        pa[l] = A4[(long)(blk + row) * (DD / 4) + kq];
    }
#pragma unroll
    for (int l = 0; l < 2; l++) {
        pwh[l] = gWh4[l * 128 + tid];
        pwl[l] = gWl4[l * 128 + tid];
    }
    // ---- stage tile 0 into buf0 ----
#pragma unroll
    for (int l = 0; l < 4; l++) {
        int fi = l * 128 + tid;
        int row = fi >> 3, kq = fi & 7;
        unsigned h0, l0, h1, l1;
        split_pack(pa[l].x, pa[l].y, h0, l0);
        split_pack(pa[l].z, pa[l].w, h1, l1);
        *(uint2*)&sAh[row * KPR + 2 * kq] = make_uint2(h0, h1);
        *(uint2*)&sAl[row * KPR + 2 * kq] = make_uint2(l0, l1);
    }
#pragma unroll
    for (int l = 0; l < 2; l++) {
        int u = l * 128 + tid;
        int row = u >> 2, q = u & 3;
        *(uint4*)&sWh[row * KPR + q * 4] = pwh[l];
        *(uint4*)&sWl[row * KPR + q * 4] = pwl[l];
    }
    // ---- LDG tile 1 ----
#pragma unroll
    for (int l = 0; l < 4; l++) {
        int fi = l * 128 + tid;
        int row = fi >> 3, kq = fi & 7;
        pa[l] = A4[(long)(blk + row) * (DD / 4) + 8 + kq];
    }
#pragma unroll
    for (int l = 0; l < 2; l++) {
        pwh[l] = gWh4[256 + l * 128 + tid];
        pwl[l] = gWl4[256 + l * 128 + tid];
    }
    __syncthreads();

    int buf = 0;
    for (int t = 0; t < NTILES; t++) {
        const int cb_ = buf * 1280;
        const int nb_ = (buf ^ 1) * 1280;

        // stage t+1 (regs) into other buffer
        if (t + 1 < NTILES) {
#pragma unroll
            for (int l = 0; l < 4; l++) {
                int fi = l * 128 + tid;
                int row = fi >> 3, kq = fi & 7;
                unsigned h0, l0, h1, l1;
                split_pack(pa[l].x, pa[l].y, h0, l0);
                split_pack(pa[l].z, pa[l].w, h1, l1);
                *(uint2*)&sAh[nb_ + row * KPR + 2 * kq] = make_uint2(h0, h1);
                *(uint2*)&sAl[nb_ + row * KPR + 2 * kq] = make_uint2(l0, l1);
            }
#pragma unroll
            for (int l = 0; l < 2; l++) {
                int u = l * 128 + tid;
                int row = u >> 2, q = u & 3;
                *(uint4*)&sWh[nb_ + row * KPR + q * 4] = pwh[l];
                *(uint4*)&sWl[nb_ + row * KPR + q * 4] = pwl[l];
            }
        }
        // LDG t+2
        if (t + 2 < NTILES) {
            int k0 = (t + 2) * 8;
#pragma unroll
            for (int l = 0; l < 4; l++) {
                int fi = l * 128 + tid;
                int row = fi >> 3, kq = fi & 7;
                pa[l] = A4[(long)(blk + row) * (DD / 4) + k0 + kq];
            }
            int w0 = (t + 2) * 256;
#pragma unroll
            for (int l = 0; l < 2; l++) {
                pwh[l] = gWh4[w0 + l * 128 + tid];
                pwl[l] = gWl4[w0 + l * 128 + tid];
            }
        }

        // compute tile t from current buffer
#pragma unroll
        for (int kc = 0; kc < 2; kc++) {
            const int kb = kc * 8;
            unsigned Ah[2][4], Al[2][4];
#pragma unroll
            for (int mt = 0; mt < 2; mt++) {
                int rb = cb_ + (wm * 32 + mt * 16 + g) * KPR + kb + c;
                Ah[mt][0] = sAh[rb];
                Ah[mt][1] = sAh[rb + 8 * KPR];
                Ah[mt][2] = sAh[rb + 4];
                Ah[mt][3] = sAh[rb + 8 * KPR + 4];
                Al[mt][0] = sAl[rb];
                Al[mt][1] = sAl[rb + 8 * KPR];
                Al[mt][2] = sAl[rb + 4];
                Al[mt][3] = sAl[rb + 8 * KPR + 4];
            }
            unsigned Bh[4][2], Bl[4][2];
#pragma unroll
            for (int nt = 0; nt < 4; nt++) {
                int cb2 = cb_ + (wn * 32 + nt * 8 + g) * KPR + kb + c;
                Bh[nt][0] = sWh[cb2];  Bh[nt][1] = sWh[cb2 + 4];
                Bl[nt][0] = sWl[cb2];  Bl[nt][1] = sWl[cb2 + 4];
            }
#pragma unroll
            for (int mt = 0; mt < 2; mt++)
#pragma unroll
                for (int nt = 0; nt < 4; nt++) {
                    mma16(acc[mt][nt], Ah[mt], Bh[nt][0], Bh[nt][1]);
                    mma16(acc[mt][nt], Ah[mt], Bl[nt][0], Bl[nt][1]);
                    mma16(acc[mt][nt], Al[mt], Bh[nt][0], Bh[nt][1]);
                }
        }
        __syncthreads();
        buf ^= 1;
    }

    // ---- epilogue ----
#pragma unroll
    for (int mt = 0; mt < 2; mt++)
#pragma unroll
        for (int nt = 0; nt < 4; nt++) {
            int r  = wm * 32 + mt * 16 + g;
            int cc = wn * 32 + nt * 8 + 2 * c;
            *(float2*)&slog[r * LR + cc]       = make_float2(acc[mt][nt][0], acc[mt][nt][1]);
            *(float2*)&slog[(r + 8) * LR + cc] = make_float2(acc[mt][nt][2], acc[mt][nt][3]);
        }
    __syncthreads();

    // zero-fill expert_indices rows for this CTA's 64 tokens (128 threads)
    {
        int tokz = blk + (tid >> 1);
        float4 z = make_float4(0.f, 0.f, 0.f, 0.f);
        float4* zb = (float4*)(out + (long)tokz * EE + (tid & 1) * 32);
#pragma unroll
        for (int q = 0; q < 8; q++) zb[q] = z;
    }

    if (tid < BM) {
        const int tok = blk + tid;
        const float* lr = slog + tid * LR;
        float mx = -1e30f, mx2 = -1e30f;
        int ag = 0;
#pragma unroll
        for (int j = 0; j < 16; j++) {
            float4 v = *(const float4*)(lr + 4 * j);
            float4 b = *(const float4*)(sbias + 4 * j);
            float xs[4] = {v.x + b.x, v.y + b.y, v.z + b.z, v.w + b.w};
#pragma unroll
            for (int q = 0; q < 4; q++) {
                float x = xs[q];
                if (x > mx)       { mx2 = mx; mx = x; ag = 4 * j + q; }
                else if (x > mx2) { mx2 = x; }
            }
        }
        float s = 0.0f;
#pragma unroll
        for (int j = 0; j < 16; j++) {
            float4 v = *(const float4*)(lr + 4 * j);
            float4 b = *(const float4*)(sbias + 4 * j);
            s += __expf(v.x + b.x - mx) + __expf(v.y + b.y - mx)
               + __expf(v.z + b.z - mx) + __expf(v.w + b.w - mx);
        }
        out[OFF_MAXP + tok] = 1.0f / s;
        g_eidx[tok] = (unsigned char)ag;

        if (mx - mx2 < TAU) {
            int p = atomicAdd(&g_cnt, 1);
            if (p < MAXFIX) g_list[p] = tok;
        }
    }
}

// Exact (double-single) recompute of 64 logits for near-tie tokens.
__global__ __launch_bounds__(512) void fixup_argmax(
    const float* __restrict__ A, const float* __restrict__ W,
    const float* __restrict__ bias)
{
    __shared__ float ph[512], pl[512];
    __shared__ double dl[64];

    int n = g_cnt;
    if (n > MAXFIX) n = MAXFIX;
    const int e   = threadIdx.x >> 3;
    const int sub = threadIdx.x & 7;

    for (int i = blockIdx.x; i < n; i += gridDim.x) {
        int tok = g_list[i];
        const float* a = A + (long)tok * DD + sub * 256;
        const float* w = W + (long)e   * DD + sub * 256;
        float shi = 0.f, slo = 0.f;
        for (int k = 0; k < 256; k++) {
            float av = __ldg(a + k), wv = __ldg(w + k);
            float p  = __fmul_rn(av, wv);
            float pe = __fmaf_rn(av, wv, -p);
            float t  = shi + p;
            float bb = t - shi;
            float er = (shi - (t - bb)) + (p - bb);
            shi = t;
            slo = slo + (er + pe);
        }
        ph[threadIdx.x] = shi;
        pl[threadIdx.x] = slo;
        __syncthreads();
        if (threadIdx.x < 64) {
            double s = (double)bias[threadIdx.x];
            for (int j = 0; j < 8; j++)
                s += (double)ph[threadIdx.x * 8 + j] + (double)pl[threadIdx.x * 8 + j];
            dl[threadIdx.x] = s;
        }
        __syncthreads();
        if (threadIdx.x == 0) {
            double mx = dl[0]; int ag = 0;
            for (int j = 1; j < 64; j++)
                if (dl[j] > mx) { mx = dl[j]; ag = j; }
            g_eidx[tok] = (unsigned char)ag;
        }
        __syncthreads();
    }
}

__global__ __launch_bounds__(256) void capacity_scan(float* __restrict__ out)
{
    const int e = blockIdx.x;
    const int b = blockIdx.y;
    const int tid = threadIdx.x;
    const int lane = tid & 31;
    const int wid = tid >> 5;

    const uint4* ids4 = (const uint4*)(g_eidx + b * SS);
    uint4 raw = ids4[tid];
    unsigned char v[16];
    *(uint4*)v = raw;

    int cnum = 0;
#pragma unroll
    for (int j = 0; j < 16; j++) cnum += (v[j] == (unsigned char)e);

    int inc = cnum;
#pragma unroll
    for (int d = 1; d < 32; d <<= 1) {
        int o = __shfl_up_sync(0xffffffffu, inc, d);
        if (lane >= d) inc += o;
    }
    __shared__ int ws[8];
    if (lane == 31) ws[wid] = inc;
    __syncthreads();
    int wpre = 0;
#pragma unroll
    for (int w = 0; w < 8; w++) wpre += (w < wid) ? ws[w] : 0;

    int run = wpre + inc - cnum;
    long tok0 = (long)b * SS + tid * 16;
#pragma unroll
    for (int j = 0; j < 16; j++) {
        if (v[j] == (unsigned char)e) {
            run++;
            if (run <= CAP) out[(tok0 + j) * EE + e] = 1.0f;
        }
    }
    if (e == 0 && b == 0 && tid == 0) g_cnt = 0;
}

extern "C" void kernel_launch(void* const* d_in, const int* in_sizes, int n_in,
                              void* d_out, int out_size)
{
    const float* A    = (const float*)d_in[0];
    const float* W    = (const float*)d_in[1];
    const float* bias = (const float*)d_in[2];
    float* out = (float*)d_out;

    split_w<<<256, 256>>>(W);
    router_mma<<<M_TOT / BM, 128>>>(A, bias, out);
    fixup_argmax<<<128, 512>>>(A, W, bias);
    capacity_scan<<<dim3(EE, BB), 256>>>(out);
}

// round 7
// speedup vs baseline: 2.2609x; 1.7208x over previous
#include <cuda_runtime.h>
#include <cuda_bf16.h>
#include <cstdint>

#define BB 4
#define SS 4096
#define DD 2048
#define EE 64
#define CAP 128
#define M_TOT (BB*SS)          // 16384 tokens
#define OFF_MAXP (M_TOT*EE)

#define BM 64
#define BK 32
#define NTILES (DD/BK)         // 64
#define KPR 20                 // u32 row stride in smem (conflict-free LDS)
#define LR 68

#define TAU_FLAG 1e-3f         // flag token if approx top-2 gap below this
#define TAU_CAND 2e-3f         // candidate experts: within this of approx max
#define MAXFIX 8192

__device__ __align__(16) unsigned char g_eidx[M_TOT];
__device__ int g_cnt = 0;
__device__ int g_list[MAXFIX];
__device__ unsigned long long g_mask[MAXFIX];
// pre-split W, tile-major: [tile t][row e][16 u32]  (u32 = bf16x2 over k-pairs)
__device__ __align__(16) unsigned gWh[NTILES * EE * 16];
__device__ __align__(16) unsigned gWl[NTILES * EE * 16];

__device__ __forceinline__ void split_pack(float x, float y, unsigned &hi, unsigned &lo) {
    __nv_bfloat16 hx = __float2bfloat16_rn(x);
    __nv_bfloat16 hy = __float2bfloat16_rn(y);
    float rx = x - __bfloat162float(hx);
    float ry = y - __bfloat162float(hy);
    __nv_bfloat16 lx = __float2bfloat16_rn(rx);
    __nv_bfloat16 ly = __float2bfloat16_rn(ry);
    __nv_bfloat162 H = __halves2bfloat162(hx, hy);
    __nv_bfloat162 L = __halves2bfloat162(lx, ly);
    hi = *reinterpret_cast<unsigned*>(&H);
    lo = *reinterpret_cast<unsigned*>(&L);
}

__device__ __forceinline__ void mma16(float c[4], const unsigned a[4],
                                      unsigned b0, unsigned b1) {
    asm volatile("mma.sync.aligned.m16n8k16.row.col.f32.bf16.bf16.f32 "
                 "{%0,%1,%2,%3}, {%4,%5,%6,%7}, {%8,%9}, {%0,%1,%2,%3};"
                 : "+f"(c[0]), "+f"(c[1]), "+f"(c[2]), "+f"(c[3])
                 : "r"(a[0]), "r"(a[1]), "r"(a[2]), "r"(a[3]), "r"(b0), "r"(b1));
}

// Pre-split W into bf16x2 hi/lo, tile-major layout.
__global__ __launch_bounds__(256) void split_w(const float* __restrict__ W)
{
    int e  = blockIdx.x >> 2;                       // 0..63
    int jg = (blockIdx.x & 3) * 256 + threadIdx.x;  // 0..1023 (k-pair)
    int k  = 2 * jg;
    float x = W[e * DD + k], y = W[e * DD + k + 1];
    unsigned h, l;
    split_pack(x, y, h, l);
    int t = jg >> 4, j = jg & 15;
    gWh[(t * EE + e) * 16 + j] = h;
    gWl[(t * EE + e) * 16 + j] = l;
}

__global__ __launch_bounds__(128, 2) void router_mma(
    const float* __restrict__ A,     // [M_TOT, DD]
    const float* __restrict__ bias,  // [EE]
    float* __restrict__ out)
{
    __shared__ __align__(16) unsigned smbuf[10240];   // 40 KB
    unsigned* sAh = smbuf;            // [2][64*KPR]
    unsigned* sAl = smbuf + 2560;
    unsigned* sWh = smbuf + 5120;
    unsigned* sWl = smbuf + 7680;
    float*    slog = (float*)smbuf;   // epilogue reuse [64][LR]
    __shared__ float sbias[EE];

    const int tid  = threadIdx.x;
    const int lane = tid & 31;
    const int wid  = tid >> 5;
    const int wm   = wid & 1;
    const int wn   = wid >> 1;
    const int g    = lane >> 2;
    const int c    = lane & 3;
    const int blk  = blockIdx.x * BM;

    if (tid < EE) sbias[tid] = bias[tid];

    const float4* __restrict__ A4 = (const float4*)A;
    const uint4*  gWh4 = (const uint4*)gWh;
    const uint4*  gWl4 = (const uint4*)gWl;

    float acc[2][4][4];
#pragma unroll
    for (int mt = 0; mt < 2; mt++)
#pragma unroll
        for (int nt = 0; nt < 4; nt++)
#pragma unroll
            for (int q = 0; q < 4; q++) acc[mt][nt][q] = 0.0f;

    float4 pa[4];
    uint4  pwh[2], pwl[2];

    // ---- LDG tile 0 ----
#pragma unroll
    for (int l = 0; l < 4; l++) {
        int fi = l * 128 + tid;
        int row = fi >> 3, kq = fi & 7;
        pa[l] = A4[(long)(blk + row) * (DD / 4) + kq];
    }
#pragma unroll
    for (int l = 0; l < 2; l++) {
        pwh[l] = gWh4[l * 128 + tid];
        pwl[l] = gWl4[l * 128 + tid];
    }
    // ---- stage tile 0 into buf0 ----
#pragma unroll
    for (int l = 0; l < 4; l++) {
        int fi = l * 128 + tid;
        int row = fi >> 3, kq = fi & 7;
        unsigned h0, l0, h1, l1;
        split_pack(pa[l].x, pa[l].y, h0, l0);
        split_pack(pa[l].z, pa[l].w, h1, l1);
        *(uint2*)&sAh[row * KPR + 2 * kq] = make_uint2(h0, h1);
        *(uint2*)&sAl[row * KPR + 2 * kq] = make_uint2(l0, l1);
    }
#pragma unroll
    for (int l = 0; l < 2; l++) {
        int u = l * 128 + tid;
        int row = u >> 2, q = u & 3;
        *(uint4*)&sWh[row * KPR + q * 4] = pwh[l];
        *(uint4*)&sWl[row * KPR + q * 4] = pwl[l];
    }
    // ---- LDG tile 1 ----
#pragma unroll
    for (int l = 0; l < 4; l++) {
        int fi = l * 128 + tid;
        int row = fi >> 3, kq = fi & 7;
        pa[l] = A4[(long)(blk + row) * (DD / 4) + 8 + kq];
    }
#pragma unroll
    for (int l = 0; l < 2; l++) {
        pwh[l] = gWh4[256 + l * 128 + tid];
        pwl[l] = gWl4[256 + l * 128 + tid];
    }
    __syncthreads();

    int buf = 0;
    for (int t = 0; t < NTILES; t++) {
        const int cb_ = buf * 1280;
        const int nb_ = (buf ^ 1) * 1280;

        if (t + 1 < NTILES) {
#pragma unroll
            for (int l = 0; l < 4; l++) {
                int fi = l * 128 + tid;
                int row = fi >> 3, kq = fi & 7;
                unsigned h0, l0, h1, l1;
                split_pack(pa[l].x, pa[l].y, h0, l0);
                split_pack(pa[l].z, pa[l].w, h1, l1);
                *(uint2*)&sAh[nb_ + row * KPR + 2 * kq] = make_uint2(h0, h1);
                *(uint2*)&sAl[nb_ + row * KPR + 2 * kq] = make_uint2(l0, l1);
            }
#pragma unroll
            for (int l = 0; l < 2; l++) {
                int u = l * 128 + tid;
                int row = u >> 2, q = u & 3;
                *(uint4*)&sWh[nb_ + row * KPR + q * 4] = pwh[l];
                *(uint4*)&sWl[nb_ + row * KPR + q * 4] = pwl[l];
            }
        }
        if (t + 2 < NTILES) {
            int k0 = (t + 2) * 8;
#pragma unroll
            for (int l = 0; l < 4; l++) {
                int fi = l * 128 + tid;
                int row = fi >> 3, kq = fi & 7;
                pa[l] = A4[(long)(blk + row) * (DD / 4) + k0 + kq];
            }
            int w0 = (t + 2) * 256;
#pragma unroll
            for (int l = 0; l < 2; l++) {
                pwh[l] = gWh4[w0 + l * 128 + tid];
                pwl[l] = gWl4[w0 + l * 128 + tid];
            }
        }

#pragma unroll
        for (int kc = 0; kc < 2; kc++) {
            const int kb = kc * 8;
            unsigned Ah[2][4], Al[2][4];
#pragma unroll
            for (int mt = 0; mt < 2; mt++) {
                int rb = cb_ + (wm * 32 + mt * 16 + g) * KPR + kb + c;
                Ah[mt][0] = sAh[rb];
                Ah[mt][1] = sAh[rb + 8 * KPR];
                Ah[mt][2] = sAh[rb + 4];
                Ah[mt][3] = sAh[rb + 8 * KPR + 4];
                Al[mt][0] = sAl[rb];
                Al[mt][1] = sAl[rb + 8 * KPR];
                Al[mt][2] = sAl[rb + 4];
                Al[mt][3] = sAl[rb + 8 * KPR + 4];
            }
            unsigned Bh[4][2], Bl[4][2];
#pragma unroll
            for (int nt = 0; nt < 4; nt++) {
                int cb2 = cb_ + (wn * 32 + nt * 8 + g) * KPR + kb + c;
                Bh[nt][0] = sWh[cb2];  Bh[nt][1] = sWh[cb2 + 4];
                Bl[nt][0] = sWl[cb2];  Bl[nt][1] = sWl[cb2 + 4];
            }
#pragma unroll
            for (int mt = 0; mt < 2; mt++)
#pragma unroll
                for (int nt = 0; nt < 4; nt++) {
                    mma16(acc[mt][nt], Ah[mt], Bh[nt][0], Bh[nt][1]);
                    mma16(acc[mt][nt], Ah[mt], Bl[nt][0], Bl[nt][1]);
                    mma16(acc[mt][nt], Al[mt], Bh[nt][0], Bh[nt][1]);
                }
        }
        __syncthreads();
        buf ^= 1;
    }

    // ---- epilogue ----
#pragma unroll
    for (int mt = 0; mt < 2; mt++)
#pragma unroll
        for (int nt = 0; nt < 4; nt++) {
            int r  = wm * 32 + mt * 16 + g;
            int cc = wn * 32 + nt * 8 + 2 * c;
            *(float2*)&slog[r * LR + cc]       = make_float2(acc[mt][nt][0], acc[mt][nt][1]);
            *(float2*)&slog[(r + 8) * LR + cc] = make_float2(acc[mt][nt][2], acc[mt][nt][3]);
        }
    __syncthreads();

    // zero-fill expert_indices rows for this CTA's 64 tokens
    {
        int tokz = blk + (tid >> 1);
        float4 z = make_float4(0.f, 0.f, 0.f, 0.f);
        float4* zb = (float4*)(out + (long)tokz * EE + (tid & 1) * 32);
#pragma unroll
        for (int q = 0; q < 8; q++) zb[q] = z;
    }

    if (tid < BM) {
        const int tok = blk + tid;
        const float* lr = slog + tid * LR;
        float mx = -1e30f, mx2 = -1e30f;
        int ag = 0;
#pragma unroll
        for (int j = 0; j < 16; j++) {
            float4 v = *(const float4*)(lr + 4 * j);
            float4 b = *(const float4*)(sbias + 4 * j);
            float xs[4] = {v.x + b.x, v.y + b.y, v.z + b.z, v.w + b.w};
#pragma unroll
            for (int q = 0; q < 4; q++) {
                float x = xs[q];
                if (x > mx)       { mx2 = mx; mx = x; ag = 4 * j + q; }
                else if (x > mx2) { mx2 = x; }
            }
        }
        float s = 0.0f;
        unsigned long long cmask = 0ull;
        const float thr = mx - TAU_CAND;
#pragma unroll
        for (int j = 0; j < 16; j++) {
            float4 v = *(const float4*)(lr + 4 * j);
            float4 b = *(const float4*)(sbias + 4 * j);
            float x0 = v.x + b.x, x1 = v.y + b.y, x2 = v.z + b.z, x3 = v.w + b.w;
            s += __expf(x0 - mx) + __expf(x1 - mx) + __expf(x2 - mx) + __expf(x3 - mx);
            if (x0 > thr) cmask |= 1ull << (4 * j);
            if (x1 > thr) cmask |= 1ull << (4 * j + 1);
            if (x2 > thr) cmask |= 1ull << (4 * j + 2);
            if (x3 > thr) cmask |= 1ull << (4 * j + 3);
        }
        out[OFF_MAXP + tok] = 1.0f / s;
        g_eidx[tok] = (unsigned char)ag;

        if (mx - mx2 < TAU_FLAG) {
            int p = atomicAdd(&g_cnt, 1);
            if (p < MAXFIX) { g_list[p] = tok; g_mask[p] = cmask; }
        }
    }
}

// One warp per flagged token: exact (fp64) logits for the few candidate
// experts only; overwrite g_eidx with the exact argmax.
__global__ __launch_bounds__(128) void fixup_argmax(
    const float* __restrict__ A, const float* __restrict__ W,
    const float* __restrict__ bias)
{
    int n = g_cnt;
    if (n > MAXFIX) n = MAXFIX;
    const int lane  = threadIdx.x & 31;
    const int warp  = (blockIdx.x * (blockDim.x >> 5)) + (threadIdx.x >> 5);
    const int nwarp = gridDim.x * (blockDim.x >> 5);

    for (int i = warp; i < n; i += nwarp) {
        int tok = g_list[i];
        unsigned long long m = g_mask[i];
        const float* a = A + (long)tok * DD;

        double best = -1e300;
        int bestE = 0;
        while (m) {
            int e = __ffsll((long long)m) - 1;
            m &= m - 1;
            const float* w = W + (long)e * DD;
            double p0 = 0.0, p1 = 0.0, p2 = 0.0, p3 = 0.0;
            for (int k = lane * 4; k < DD; k += 128) {
                float4 av = *(const float4*)(a + k);
                float4 wv = *(const float4*)(w + k);
                p0 = fma((double)av.x, (double)wv.x, p0);
                p1 = fma((double)av.y, (double)wv.y, p1);
                p2 = fma((double)av.z, (double)wv.z, p2);
                p3 = fma((double)av.w, (double)wv.w, p3);
            }
            double ps = (p0 + p1) + (p2 + p3);
#pragma unroll
            for (int d = 16; d > 0; d >>= 1)
                ps += __shfl_xor_sync(0xffffffffu, ps, d);
            ps += (double)bias[e];
            if (ps > best) { best = ps; bestE = e; }  // ascending e: first wins ties
        }
        if (lane == 0) g_eidx[tok] = (unsigned char)bestE;
    }
}

__global__ __launch_bounds__(256) void capacity_scan(float* __restrict__ out)
{
    const int e = blockIdx.x;
    const int b = blockIdx.y;
    const int tid = threadIdx.x;
    const int lane = tid & 31;
    const int wid = tid >> 5;

    const uint4* ids4 = (const uint4*)(g_eidx + b * SS);
    uint4 raw = ids4[tid];
    unsigned char v[16];
    *(uint4*)v = raw;

    int cnum = 0;
#pragma unroll
    for (int j = 0; j < 16; j++) cnum += (v[j] == (unsigned char)e);

    int inc = cnum;
#pragma unroll
    for (int d = 1; d < 32; d <<= 1) {
        int o = __shfl_up_sync(0xffffffffu, inc, d);
        if (lane >= d) inc += o;
    }
    __shared__ int ws[8];
    if (lane == 31) ws[wid] = inc;
    __syncthreads();
    int wpre = 0;
#pragma unroll
    for (int w = 0; w < 8; w++) wpre += (w < wid) ? ws[w] : 0;

    int run = wpre + inc - cnum;
    long tok0 = (long)b * SS + tid * 16;
#pragma unroll
    for (int j = 0; j < 16; j++) {
        if (v[j] == (unsigned char)e) {
            run++;
            if (run <= CAP) out[(tok0 + j) * EE + e] = 1.0f;
        }
    }
    if (e == 0 && b == 0 && tid == 0) g_cnt = 0;
}

extern "C" void kernel_launch(void* const* d_in, const int* in_sizes, int n_in,
                              void* d_out, int out_size)
{
    const float* A    = (const float*)d_in[0];
    const float* W    = (const float*)d_in[1];
    const float* bias = (const float*)d_in[2];
    float* out = (float*)d_out;

    split_w<<<256, 256>>>(W);
    router_mma<<<M_TOT / BM, 128>>>(A, bias, out);
    fixup_argmax<<<64, 128>>>(A, W, bias);
    capacity_scan<<<dim3(EE, BB), 256>>>(out);
}

// round 10
// speedup vs baseline: 2.3087x; 1.0212x over previous
#include <cuda_runtime.h>
#include <cuda_bf16.h>
#include <cstdint>

#define BB 4
#define SS 4096
#define DD 2048
#define EE 64
#define CAP 128
#define M_TOT (BB*SS)          // 16384 tokens
#define OFF_MAXP (M_TOT*EE)

#define BM 64
#define BK 32
#define NTILES (DD/BK)         // 64 total k-tiles
#define TPH 32                 // tiles per k-half (in-CTA split-K=2)
#define KPR 20                 // u32 row stride in smem (conflict-free LDS)
#define LR 68                  // slog f32 row stride

#define TAU_FLAG 1e-3f
#define TAU_CAND 2e-3f
#define MAXFIX 8192

__device__ __align__(16) unsigned char g_eidx[M_TOT];
__device__ int g_cnt = 0;
__device__ int g_list[MAXFIX];
__device__ unsigned long long g_mask[MAXFIX];
// pre-split W, tile-major: [tile t][row e][16 u32]
__device__ __align__(16) unsigned gWh[NTILES * EE * 16];
__device__ __align__(16) unsigned gWl[NTILES * EE * 16];

__device__ __forceinline__ void split_pack(float x, float y, unsigned &hi, unsigned &lo) {
    __nv_bfloat16 hx = __float2bfloat16_rn(x);
    __nv_bfloat16 hy = __float2bfloat16_rn(y);
    float rx = x - __bfloat162float(hx);
    float ry = y - __bfloat162float(hy);
    __nv_bfloat16 lx = __float2bfloat16_rn(rx);
    __nv_bfloat16 ly = __float2bfloat16_rn(ry);
    __nv_bfloat162 H = __halves2bfloat162(hx, hy);
    __nv_bfloat162 L = __halves2bfloat162(lx, ly);
    hi = *reinterpret_cast<unsigned*>(&H);
    lo = *reinterpret_cast<unsigned*>(&L);
}

__device__ __forceinline__ void mma16(float c[4], const unsigned a[4],
                                      unsigned b0, unsigned b1) {
    asm volatile("mma.sync.aligned.m16n8k16.row.col.f32.bf16.bf16.f32 "
                 "{%0,%1,%2,%3}, {%4,%5,%6,%7}, {%8,%9}, {%0,%1,%2,%3};"
                 : "+f"(c[0]), "+f"(c[1]), "+f"(c[2]), "+f"(c[3])
                 : "r"(a[0]), "r"(a[1]), "r"(a[2]), "r"(a[3]), "r"(b0), "r"(b1));
}

__global__ __launch_bounds__(256) void split_w(const float* __restrict__ W)
{
    int e  = blockIdx.x >> 2;
    int jg = (blockIdx.x & 3) * 256 + threadIdx.x;
    int k  = 2 * jg;
    float x = W[e * DD + k], y = W[e * DD + k + 1];
    unsigned h, l;
    split_pack(x, y, h, l);
    int t = jg >> 4, j = jg & 15;
    gWh[(t * EE + e) * 16 + j] = h;
    gWl[(t * EE + e) * 16 + j] = l;
}

__global__ __launch_bounds__(256, 2) void router_mma(
    const float* __restrict__ A,     // [M_TOT, DD]
    const float* __restrict__ bias,  // [EE]
    float* __restrict__ out)
{
    __shared__ __align__(16) unsigned smbuf[10240];   // 40 KB: 2 halves x 5120
    __shared__ float sbias[EE];
    float* slog = (float*)smbuf;      // epilogue reuse [64][LR]

    const int tid  = threadIdx.x;
    const int lane = tid & 31;
    const int wid  = tid >> 5;
    const int h    = tid >> 7;        // k-half 0/1
    const int wt   = tid & 127;       // thread within half
    const int w2   = wid & 3;         // warp within half
    const int wm   = w2 >> 1;
    const int wn   = w2 & 1;
    const int g    = lane >> 2;
    const int c    = lane & 3;
    const int blk  = blockIdx.x * BM;

    unsigned* sAh = smbuf + h * 5120;  // [64][KPR]
    unsigned* sAl = sAh + 1280;
    unsigned* sWh = sAh + 2560;
    unsigned* sWl = sAh + 3840;

    if (tid < EE) sbias[tid] = bias[tid];

    const float4* __restrict__ A4 = (const float4*)A;
    const uint4*  gWh4 = (const uint4*)gWh;
    const uint4*  gWl4 = (const uint4*)gWl;

    const int kqb = h * (DD / 4 / 2);  // float4 base offset in A row
    const int tb  = h * TPH;           // W tile base for this half

    float acc[2][4][4];
#pragma unroll
    for (int mt = 0; mt < 2; mt++)
#pragma unroll
        for (int nt = 0; nt < 4; nt++)
#pragma unroll
            for (int q = 0; q < 4; q++) acc[mt][nt][q] = 0.0f;

    float4 pa[4];
    uint4  pwh[2], pwl[2];

    // ---- LDG tile 0 of this half ----
#pragma unroll
    for (int l = 0; l < 4; l++) {
        int fi = l * 128 + wt;
        int row = fi >> 3, kq = fi & 7;
        pa[l] = A4[(long)(blk + row) * (DD / 4) + kqb + kq];
    }
#pragma unroll
    for (int l = 0; l < 2; l++) {
        pwh[l] = gWh4[tb * 256 + l * 128 + wt];
        pwl[l] = gWl4[tb * 256 + l * 128 + wt];
    }
    // ---- stage tile 0 ----
#pragma unroll
    for (int l = 0; l < 4; l++) {
        int fi = l * 128 + wt;
        int row = fi >> 3, kq = fi & 7;
        unsigned h0, l0, h1, l1;
        split_pack(pa[l].x, pa[l].y, h0, l0);
        split_pack(pa[l].z, pa[l].w, h1, l1);
        *(uint2*)&sAh[row * KPR + 2 * kq] = make_uint2(h0, h1);
        *(uint2*)&sAl[row * KPR + 2 * kq] = make_uint2(l0, l1);
    }
#pragma unroll
    for (int l = 0; l < 2; l++) {
        int u = l * 128 + wt;
        int row = u >> 2, q = u & 3;
        *(uint4*)&sWh[row * KPR + q * 4] = pwh[l];
        *(uint4*)&sWl[row * KPR + q * 4] = pwl[l];
    }
    // ---- LDG tile 1 ----
#pragma unroll
    for (int l = 0; l < 4; l++) {
        int fi = l * 128 + wt;
        int row = fi >> 3, kq = fi & 7;
        pa[l] = A4[(long)(blk + row) * (DD / 4) + kqb + 8 + kq];
    }
#pragma unroll
    for (int l = 0; l < 2; l++) {
        pwh[l] = gWh4[(tb + 1) * 256 + l * 128 + wt];
        pwl[l] = gWl4[(tb + 1) * 256 + l * 128 + wt];
    }
    __syncthreads();

    for (int t = 0; t < TPH; t++) {
        // compute tile t
#pragma unroll
        for (int kc = 0; kc < 2; kc++) {
            const int kb = kc * 8;
            unsigned Ah[2][4], Al[2][4];
#pragma unroll
            for (int mt = 0; mt < 2; mt++) {
                int rb = (wm * 32 + mt * 16 + g) * KPR + kb + c;
                Ah[mt][0] = sAh[rb];
                Ah[mt][1] = sAh[rb + 8 * KPR];
                Ah[mt][2] = sAh[rb + 4];
                Ah[mt][3] = sAh[rb + 8 * KPR + 4];
                Al[mt][0] = sAl[rb];
                Al[mt][1] = sAl[rb + 8 * KPR];
                Al[mt][2] = sAl[rb + 4];
                Al[mt][3] = sAl[rb + 8 * KPR + 4];
            }
            unsigned Bh[4][2], Bl[4][2];
#pragma unroll
            for (int nt = 0; nt < 4; nt++) {
                int cb2 = (wn * 32 + nt * 8 + g) * KPR + kb + c;
                Bh[nt][0] = sWh[cb2];  Bh[nt][1] = sWh[cb2 + 4];
                Bl[nt][0] = sWl[cb2];  Bl[nt][1] = sWl[cb2 + 4];
            }
#pragma unroll
            for (int mt = 0; mt < 2; mt++)
#pragma unroll
                for (int nt = 0; nt < 4; nt++) {
                    mma16(acc[mt][nt], Ah[mt], Bh[nt][0], Bh[nt][1]);
                    mma16(acc[mt][nt], Ah[mt], Bl[nt][0], Bl[nt][1]);
                    mma16(acc[mt][nt], Al[mt], Bh[nt][0], Bh[nt][1]);
                }
        }
        __syncthreads();

        // stage t+1 from regs; LDG t+2
        if (t + 1 < TPH) {
#pragma unroll
            for (int l = 0; l < 4; l++) {
                int fi = l * 128 + wt;
                int row = fi >> 3, kq = fi & 7;
                unsigned h0, l0, h1, l1;
                split_pack(pa[l].x, pa[l].y, h0, l0);
                split_pack(pa[l].z, pa[l].w, h1, l1);
                *(uint2*)&sAh[row * KPR + 2 * kq] = make_uint2(h0, h1);
                *(uint2*)&sAl[row * KPR + 2 * kq] = make_uint2(l0, l1);
            }
#pragma unroll
            for (int l = 0; l < 2; l++) {
                int u = l * 128 + wt;
                int row = u >> 2, q = u & 3;
                *(uint4*)&sWh[row * KPR + q * 4] = pwh[l];
                *(uint4*)&sWl[row * KPR + q * 4] = pwl[l];
            }
            if (t + 2 < TPH) {
                int k0 = (t + 2) * 8;
#pragma unroll
                for (int l = 0; l < 4; l++) {
                    int fi = l * 128 + wt;
                    int row = fi >> 3, kq = fi & 7;
                    pa[l] = A4[(long)(blk + row) * (DD / 4) + kqb + k0 + kq];
                }
                int w0 = (tb + t + 2) * 256;
#pragma unroll
                for (int l = 0; l < 2; l++) {
                    pwh[l] = gWh4[w0 + l * 128 + wt];
                    pwl[l] = gWl4[w0 + l * 128 + wt];
                }
            }
            __syncthreads();
        }
    }

    // ---- epilogue: half 0 stores partial, half 1 adds ----
    __syncthreads();
    if (h == 0) {
#pragma unroll
        for (int mt = 0; mt < 2; mt++)
#pragma unroll
            for (int nt = 0; nt < 4; nt++) {
                int r  = wm * 32 + mt * 16 + g;
                int cc = wn * 32 + nt * 8 + 2 * c;
                *(float2*)&slog[r * LR + cc]       = make_float2(acc[mt][nt][0], acc[mt][nt][1]);
                *(float2*)&slog[(r + 8) * LR + cc] = make_float2(acc[mt][nt][2], acc[mt][nt][3]);
            }
    }
    __syncthreads();
    if (h == 1) {
#pragma unroll
        for (int mt = 0; mt < 2; mt++)
#pragma unroll
            for (int nt = 0; nt < 4; nt++) {
                int r  = wm * 32 + mt * 16 + g;
                int cc = wn * 32 + nt * 8 + 2 * c;
                float2 v0 = *(float2*)&slog[r * LR + cc];
                float2 v1 = *(float2*)&slog[(r + 8) * LR + cc];
                *(float2*)&slog[r * LR + cc] =
                    make_float2(v0.x + acc[mt][nt][0], v0.y + acc[mt][nt][1]);
                *(float2*)&slog[(r + 8) * LR + cc] =
                    make_float2(v1.x + acc[mt][nt][2], v1.y + acc[mt][nt][3]);
            }
    }
    __syncthreads();

    // zero-fill expert_indices rows for this CTA's 64 tokens (256 threads)
    {
        int tokz = blk + (tid >> 2);
        float4 z = make_float4(0.f, 0.f, 0.f, 0.f);
        float4* zb = (float4*)(out + (long)tokz * EE + (tid & 3) * 16);
#pragma unroll
        for (int q = 0; q < 4; q++) zb[q] = z;
    }

    if (tid < BM) {
        const int tok = blk + tid;
        const float* lr = slog + tid * LR;
        float x[EE];
#pragma unroll
        for (int j = 0; j < 16; j++) {
            float4 v = *(const float4*)(lr + 4 * j);
            float4 b = *(const float4*)(sbias + 4 * j);
            x[4 * j]     = v.x + b.x;
            x[4 * j + 1] = v.y + b.y;
            x[4 * j + 2] = v.z + b.z;
            x[4 * j + 3] = v.w + b.w;
        }
        float mx = -1e30f, mx2 = -1e30f;
        int ag = 0;
#pragma unroll
        for (int j = 0; j < EE; j++) {
            float v = x[j];
            if (v > mx)       { mx2 = mx; mx = v; ag = j; }
            else if (v > mx2) { mx2 = v; }
        }
        float s = 0.0f;
        unsigned long long cmask = 0ull;
        const float thr = mx - TAU_CAND;
#pragma unroll
        for (int j = 0; j < EE; j++) {
            s += __expf(x[j] - mx);
            if (x[j] > thr) cmask |= 1ull << j;
        }
        out[OFF_MAXP + tok] = 1.0f / s;
        g_eidx[tok] = (unsigned char)ag;

        if (mx - mx2 < TAU_FLAG) {
            int p = atomicAdd(&g_cnt, 1);
            if (p < MAXFIX) { g_list[p] = tok; g_mask[p] = cmask; }
        }
    }
}

// One warp per flagged token: exact (fp64) logits for candidate experts only.
__global__ __launch_bounds__(128) void fixup_argmax(
    const float* __restrict__ A, const float* __restrict__ W,
    const float* __restrict__ bias)
{
    int n = g_cnt;
    if (n > MAXFIX) n = MAXFIX;
    const int lane  = threadIdx.x & 31;
    const int warp  = (blockIdx.x * (blockDim.x >> 5)) + (threadIdx.x >> 5);
    const int nwarp = gridDim.x * (blockDim.x >> 5);

    for (int i = warp; i < n; i += nwarp) {
        int tok = g_list[i];
        unsigned long long m = g_mask[i];
        const float* a = A + (long)tok * DD;

        double best = -1e300;
        int bestE = 0;
        while (m) {
            int e = __ffsll((long long)m) - 1;
            m &= m - 1;
            const float* w = W + (long)e * DD;
            double p0 = 0.0, p1 = 0.0, p2 = 0.0, p3 = 0.0;
            for (int k = lane * 4; k < DD; k += 128) {
                float4 av = *(const float4*)(a + k);
                float4 wv = *(const float4*)(w + k);
                p0 = fma((double)av.x, (double)wv.x, p0);
                p1 = fma((double)av.y, (double)wv.y, p1);
                p2 = fma((double)av.z, (double)wv.z, p2);
                p3 = fma((double)av.w, (double)wv.w, p3);
            }
            double ps = (p0 + p1) + (p2 + p3);
#pragma unroll
            for (int d = 16; d > 0; d >>= 1)
                ps += __shfl_xor_sync(0xffffffffu, ps, d);
            ps += (double)bias[e];
            if (ps > best) { best = ps; bestE = e; }
        }
        if (lane == 0) g_eidx[tok] = (unsigned char)bestE;
    }
}

__global__ __launch_bounds__(256) void capacity_scan(float* __restrict__ out)
{
    const int e = blockIdx.x;
    const int b = blockIdx.y;
    const int tid = threadIdx.x;
    const int lane = tid & 31;
    const int wid = tid >> 5;

    const uint4* ids4 = (const uint4*)(g_eidx + b * SS);
    uint4 raw = ids4[tid];
    unsigned char v[16];
    *(uint4*)v = raw;

    int cnum = 0;
#pragma unroll
    for (int j = 0; j < 16; j++) cnum += (v[j] == (unsigned char)e);

    int inc = cnum;
#pragma unroll
    for (int d = 1; d < 32; d <<= 1) {
        int o = __shfl_up_sync(0xffffffffu, inc, d);
        if (lane >= d) inc += o;
    }
    __shared__ int ws[8];
    if (lane == 31) ws[wid] = inc;
    __syncthreads();
    int wpre = 0;
#pragma unroll
    for (int w = 0; w < 8; w++) wpre += (w < wid) ? ws[w] : 0;

    int run = wpre + inc - cnum;
    long tok0 = (long)b * SS + tid * 16;
#pragma unroll
    for (int j = 0; j < 16; j++) {
        if (v[j] == (unsigned char)e) {
            run++;
            if (run <= CAP) out[(tok0 + j) * EE + e] = 1.0f;
        }
    }
    if (e == 0 && b == 0 && tid == 0) g_cnt = 0;
}

extern "C" void kernel_launch(void* const* d_in, const int* in_sizes, int n_in,
                              void* d_out, int out_size)
{
    const float* A    = (const float*)d_in[0];
    const float* W    = (const float*)d_in[1];
    const float* bias = (const float*)d_in[2];
    float* out = (float*)d_out;

    split_w<<<256, 256>>>(W);
    router_mma<<<M_TOT / BM, 256>>>(A, bias, out);
    fixup_argmax<<<64, 128>>>(A, W, bias);
    capacity_scan<<<dim3(EE, BB), 256>>>(out);
}